// round 10
// baseline (speedup 1.0000x reference)
#include <cuda_runtime.h>
#include <cuda_bf16.h>
#include <cstdint>

// ---------------- problem geometry (static) ----------------
#define CC   96
#define HDIM 64
#define WDIM 64
#define HW   4096
#define DHW  131072
#define CDHW (CC*DHW)
#define D2   16
#define H2   32
#define W2   32
#define OSP  16384
#define KDIM 768
#define NDIM 192
#define NCHK 4                   // K chunks of 192 (one octant-pair each)
#define NCTA 512                 // 32768 rows / 64

// ---------------- smem layout (bytes) ----------------
#define ASTR 400                 // 192 bf16 + 8 pad ; conflict-free for ldmatrix
#define SZ_PLANE (64*ASTR)       // 25600
#define BUFSZ (2*SZ_PLANE)       // 51200 (hi+lo planes)
#define OFF_PS   (2*BUFSZ)       // 102400 : ps[256]*2
#define OFF_RSTD (OFF_PS+2048)   // 104448 : rstd[64]
#define OFF_MRS  (OFF_RSTD+256)  // 104704 : mu*rstd[64]
#define OFF_GW   (OFF_MRS+256)   // 104960 : gW[192]
#define OFF_BW   (OFF_GW+768)    // 105728 : bW[192]
#define SMEM_TOTAL (OFF_BW+768)  // 106496 -> 2 CTAs/SM (212992 <= 228KB)
#define CSTR 65                  // epilogue staging stride (floats)

// ---------------- prep outputs ----------------
// B fragments: [kt 0..47][ntile 0..23][lane 0..31] = {bh0,bh1,bl0,bl1}
__device__ __align__(16) uint4 g_Bf[48*24*32];
// vec partials: [kblk 0..31][0:gamma@W,1:beta@W][n 0..191]
__device__ float g_vpart[32*2*192];

// ---------------- helpers ----------------
__device__ __forceinline__ uint32_t smem_u32(const void* p) {
    uint32_t a;
    asm("{ .reg .u64 t; cvta.to.shared.u64 t, %1; cvt.u32.u64 %0, t; }" : "=r"(a) : "l"(p));
    return a;
}
__device__ __forceinline__ void ldsm4(uint32_t* r, uint32_t addr) {
    asm volatile("ldmatrix.sync.aligned.m8n8.x4.shared.b16 {%0,%1,%2,%3}, [%4];"
                 : "=r"(r[0]), "=r"(r[1]), "=r"(r[2]), "=r"(r[3]) : "r"(addr));
}
__device__ __forceinline__ void mma_bf16(float* c, const uint32_t* a, uint32_t b0, uint32_t b1) {
    asm volatile("mma.sync.aligned.m16n8k16.row.col.f32.bf16.bf16.f32 "
                 "{%0,%1,%2,%3}, {%4,%5,%6,%7}, {%8,%9}, {%0,%1,%2,%3};"
                 : "+f"(c[0]), "+f"(c[1]), "+f"(c[2]), "+f"(c[3])
                 : "r"(a[0]), "r"(a[1]), "r"(a[2]), "r"(a[3]), "r"(b0), "r"(b1));
}
// split (a,b) -> packed bf16 hi pair + lo pair
__device__ __forceinline__ void split2(float a, float b, uint32_t& hi, uint32_t& lo) {
    __nv_bfloat162 h = __floats2bfloat162_rn(a, b);
    uint32_t hu = *(uint32_t*)&h;
    float ha = __uint_as_float(hu << 16);
    float hb = __uint_as_float(hu & 0xffff0000u);
    __nv_bfloat162 l = __floats2bfloat162_rn(a - ha, b - hb);
    hi = hu; lo = *(uint32_t*)&l;
}

// ---------------- prep: B fragments + vec partials (single kernel) ----------------
// 288 blocks x 192 threads. tid<128: one B fragment. Blocks 0..31: vec partials.
__global__ void prep_kernel(const float* __restrict__ gamma,
                            const float* __restrict__ beta,
                            const float* __restrict__ w) {
    const int tid = threadIdx.x;
    const int blk = blockIdx.x;

    if (tid < 128) {
        const int idx = blk * 128 + tid;   // 0..36863
        const int kt   = idx / 768;
        const int rem  = idx - kt * 768;
        const int nt   = rem >> 5;
        const int lane = rem & 31;
        const int n  = nt * 8 + (lane >> 2);
        const int k0 = kt * 16 + (lane & 3) * 2;

        float w00 = gamma[k0]     * w[(k0)     * NDIM + n];
        float w01 = gamma[k0 + 1] * w[(k0 + 1) * NDIM + n];
        float w10 = gamma[k0 + 8] * w[(k0 + 8) * NDIM + n];
        float w11 = gamma[k0 + 9] * w[(k0 + 9) * NDIM + n];

        uint32_t bh0, bl0, bh1, bl1;
        split2(w00, w01, bh0, bl0);
        split2(w10, w11, bh1, bl1);
        g_Bf[idx] = make_uint4(bh0, bh1, bl0, bl1);
    }
    if (blk < 32) {
        const int n  = tid;                // 0..191
        const int k0 = blk * 24;
        float sg = 0.f, sb = 0.f;
        #pragma unroll 4
        for (int k = k0; k < k0 + 24; k++) {
            float wv = __ldg(&w[k * NDIM + n]);
            sg += __ldg(&gamma[k]) * wv;
            sb += __ldg(&beta[k])  * wv;
        }
        g_vpart[blk * 384 + n]       = sg;
        g_vpart[blk * 384 + 192 + n] = sb;
    }
}

// ---------------- fused single-pass gather + raw-GEMM + LN-affine epilogue ----------------
// grid 512 CTAs x 256 threads, 2 CTAs/SM; CTA computes rows [bid*64,+64) x 192 cols.
// Warp layout 1(m) x 8(n): no B duplication. Double-buffered A; one barrier per
// chunk; fill(next) issues before mma(cur) so gather LDGs hide under HMMA.
__global__ __launch_bounds__(256, 2)
void pm_kernel(const float* __restrict__ x, float* __restrict__ out) {
    extern __shared__ char smem[];
    const uint32_t sbase = smem_u32(smem);
    const int tid  = threadIdx.x;
    const int bid  = blockIdx.x;
    const int lane = tid & 31;
    const int wid  = tid >> 5;
    const int r    = tid & 63;    // A row this thread fills
    const int q    = tid >> 6;    // c-quarter within chunk (0..3)

    const int grp = bid * 2 + (r >> 5);
    const int h2i = grp & 31, d2i = (grp >> 5) & 15, bi = grp >> 9;
    const float* xr = x + (size_t)bi * CDHW + (2 * d2i) * HW + (2 * h2i) * WDIM + 2 * (r & 31);

    const uint32_t aoff = (uint32_t)(lane & 15) * ASTR + (lane >> 4) * 16;
    const int start = ((bid >> 2) & 1) * 2;   // chunk-schedule rotation

    float acc[4][3][4];
    #pragma unroll
    for (int mt = 0; mt < 4; mt++)
        #pragma unroll
        for (int nt = 0; nt < 3; nt++)
            #pragma unroll
            for (int e = 0; e < 4; e++) acc[mt][nt][e] = 0.f;

    float s = 0.f, s2 = 0.f;
    const int cbase = q * 24;

    // ---- fill chunk ch into buffer buf: raw y -> bf16 hi/lo + stats ----
    auto fill = [&](int ch, int buf) {
        char* dst = smem + buf * BUFSZ + (uint32_t)r * ASTR;
        const float* xc = xr + (ch >> 1) * HW + (ch & 1) * WDIM;
        int c = cbase;
        #pragma unroll
        for (int j = 0; j < 3; j++) {
            uint32_t h0[4], h1[4], l0[4], l1[4];
            #pragma unroll
            for (int t = 0; t < 4; t++, c += 2) {
                float2 va = *(const float2*)(xc + (size_t)c * DHW);
                float2 vb = *(const float2*)(xc + (size_t)(c + 1) * DHW);
                s  += (va.x + va.y) + (vb.x + vb.y);
                s2 += va.x * va.x + va.y * va.y + vb.x * vb.x + vb.y * vb.y;
                split2(va.x, vb.x, h0[t], l0[t]);   // kl = c, c+1   (w=0 octant)
                split2(va.y, vb.y, h1[t], l1[t]);   // kl = 96+c,+1  (w=1 octant)
            }
            const int c0 = cbase + 8 * j;           // 16B-aligned
            *(uint4*)(dst + 2 * c0)                  = make_uint4(h0[0], h0[1], h0[2], h0[3]);
            *(uint4*)(dst + 192 + 2 * c0)            = make_uint4(h1[0], h1[1], h1[2], h1[3]);
            *(uint4*)(dst + SZ_PLANE + 2 * c0)       = make_uint4(l0[0], l0[1], l0[2], l0[3]);
            *(uint4*)(dst + SZ_PLANE + 192 + 2 * c0) = make_uint4(l1[0], l1[1], l1[2], l1[3]);
        }
    };

    // ---- mma over one chunk from buffer buf (12 k-steps, 3 split terms) ----
    auto mmachunk = [&](int ch, int buf) {
        const uint32_t abase = sbase + buf * BUFSZ;
        const uint4* bp = g_Bf + ((size_t)(ch * 12) * 24 + wid * 3) * 32 + lane;
        uint32_t bb[2][3][4];
        #pragma unroll
        for (int nt = 0; nt < 3; nt++) {
            uint4 v = __ldg(bp + nt * 32);
            bb[0][nt][0] = v.x; bb[0][nt][1] = v.y; bb[0][nt][2] = v.z; bb[0][nt][3] = v.w;
        }
        #pragma unroll
        for (int ks = 0; ks < 12; ks++) {
            if (ks < 11) {
                const uint4* bp2 = bp + (size_t)(ks + 1) * 24 * 32;
                #pragma unroll
                for (int nt = 0; nt < 3; nt++) {
                    uint4 v = __ldg(bp2 + nt * 32);
                    bb[(ks + 1) & 1][nt][0] = v.x; bb[(ks + 1) & 1][nt][1] = v.y;
                    bb[(ks + 1) & 1][nt][2] = v.z; bb[(ks + 1) & 1][nt][3] = v.w;
                }
            }
            uint32_t af[4][4], al[4][4];
            #pragma unroll
            for (int mt = 0; mt < 4; mt++)
                ldsm4(af[mt], abase + aoff + mt * (16 * ASTR) + ks * 32);
            #pragma unroll
            for (int mt = 0; mt < 4; mt++)
                ldsm4(al[mt], abase + SZ_PLANE + aoff + mt * (16 * ASTR) + ks * 32);
            uint32_t (*B)[4] = bb[ks & 1];
            #pragma unroll
            for (int mt = 0; mt < 4; mt++)
                #pragma unroll
                for (int nt = 0; nt < 3; nt++)
                    mma_bf16(acc[mt][nt], af[mt], B[nt][0], B[nt][1]);
            #pragma unroll
            for (int mt = 0; mt < 4; mt++)
                #pragma unroll
                for (int nt = 0; nt < 3; nt++)
                    mma_bf16(acc[mt][nt], al[mt], B[nt][0], B[nt][1]);
            #pragma unroll
            for (int mt = 0; mt < 4; mt++)
                #pragma unroll
                for (int nt = 0; nt < 3; nt++)
                    mma_bf16(acc[mt][nt], af[mt], B[nt][2], B[nt][3]);
        }
    };

    fill(start, 0);
    #pragma unroll 1
    for (int i = 0; i < NCHK; i++) {
        __syncthreads();
        if (i < NCHK - 1) fill((start + i + 1) & 3, (i + 1) & 1);
        mmachunk((start + i) & 3, i & 1);
    }
    __syncthreads();

    // ---- LN stats + vec reduction ----
    float* ps = (float*)(smem + OFF_PS);
    ps[tid] = s; ps[256 + tid] = s2;
    __syncthreads();
    float* rstd_s = (float*)(smem + OFF_RSTD);
    float* mrs_s  = (float*)(smem + OFF_MRS);
    float* gW_s   = (float*)(smem + OFF_GW);
    float* bW_s   = (float*)(smem + OFF_BW);
    if (tid < 64) {
        float S = 0.f, S2 = 0.f;
        #pragma unroll
        for (int j = 0; j < 4; j++) { S += ps[j * 64 + tid]; S2 += ps[256 + j * 64 + tid]; }
        float mu  = S * (1.f / 768.f);
        float var = S2 * (1.f / 768.f) - mu * mu;
        float rstd = rsqrtf(var + 1e-5f);
        rstd_s[tid] = rstd;
        mrs_s[tid]  = mu * rstd;
    }
    #pragma unroll 1
    for (int j = tid; j < 384; j += 256) {
        float S = 0.f;
        #pragma unroll 8
        for (int p = 0; p < 32; p++) S += __ldg(&g_vpart[p * 384 + j]);
        if (j < 192) gW_s[j] = S;
        else         bW_s[j - 192] = S;
    }
    __syncthreads();

    // ---- epilogue: stage C transposed in smem (buf0), coalesced affine store ----
    float* Csm = (float*)smem;
    #pragma unroll
    for (int mt = 0; mt < 4; mt++) {
        int row = mt * 16 + (lane >> 2);
        #pragma unroll
        for (int nt = 0; nt < 3; nt++) {
            int n = wid * 24 + nt * 8 + 2 * (lane & 3);
            Csm[n * CSTR + row]           = acc[mt][nt][0];
            Csm[(n + 1) * CSTR + row]     = acc[mt][nt][1];
            Csm[n * CSTR + row + 8]       = acc[mt][nt][2];
            Csm[(n + 1) * CSTR + row + 8] = acc[mt][nt][3];
        }
    }
    __syncthreads();
    #pragma unroll 8
    for (int i = 0; i < 48; i++) {
        int idx = tid + 256 * i;
        int n = idx >> 6, row = idx & 63;
        float val = rstd_s[row] * Csm[n * CSTR + row] - mrs_s[row] * gW_s[n] + bW_s[n];
        int grp2 = bid * 2 + (row >> 5);
        int h2o = grp2 & 31, d2o = (grp2 >> 5) & 15, bo = grp2 >> 9;
        out[(size_t)bo * NDIM * OSP + (size_t)n * OSP + d2o * (H2 * W2) + h2o * W2 + (row & 31)] = val;
    }
}

// ---------------- launch ----------------
extern "C" void kernel_launch(void* const* d_in, const int* in_sizes, int n_in,
                              void* d_out, int out_size) {
    const float* x     = (const float*)d_in[0];
    const float* gamma = (const float*)d_in[1];
    const float* beta  = (const float*)d_in[2];
    const float* w     = (const float*)d_in[3];
    float* out = (float*)d_out;

    cudaFuncSetAttribute(pm_kernel, cudaFuncAttributeMaxDynamicSharedMemorySize, SMEM_TOTAL);

    prep_kernel<<<288, 192>>>(gamma, beta, w);
    pm_kernel<<<NCTA, 256, SMEM_TOTAL>>>(x, out);
}

// round 11
// speedup vs baseline: 1.0700x; 1.0700x over previous
#include <cuda_runtime.h>
#include <cuda_bf16.h>
#include <cstdint>

// ---------------- problem geometry (static) ----------------
#define CC   96
#define HDIM 64
#define WDIM 64
#define HW   4096
#define DHW  131072
#define CDHW (CC*DHW)
#define D2   16
#define H2   32
#define W2   32
#define OSP  16384
#define KDIM 768
#define NDIM 192
#define NCHK 4                   // K chunks of 192 (one octant-pair each)
#define NCTA 512                 // 32768 rows / 64

// ---------------- smem layout (bytes) ----------------
#define ASTR 400                 // 192 bf16 + 8 pad ; conflict-free for ldmatrix
#define SZ_PLANE (64*ASTR)       // 25600
#define OFF_AL SZ_PLANE          // lo plane
#define OFF_PS   (2*SZ_PLANE)    // 51200 : ps[256]*2
#define OFF_RSTD (OFF_PS+2048)   // 53248 : rstd[64]
#define OFF_MRS  (OFF_RSTD+256)  // 53504 : mu*rstd[64]
#define OFF_GW   (OFF_MRS+256)   // 53760 : gW[192]
#define OFF_BW   (OFF_GW+768)    // 54528 : bW[192]
#define SMEM_TOTAL (OFF_BW+768)  // 55296 -> 2 CTAs/SM
#define CSTR 65                  // epilogue staging stride (floats)

// ---------------- prep outputs ----------------
// B fragments: [kt 0..47][ntile 0..23][lane 0..31] = {bh0,bh1,bl0,bl1}
__device__ __align__(16) uint4 g_Bf[48*24*32];
// vec partials: [kblk 0..31][0:gamma@W,1:beta@W][n 0..191]
__device__ float g_vpart[32*2*192];

// ---------------- helpers ----------------
__device__ __forceinline__ uint32_t smem_u32(const void* p) {
    uint32_t a;
    asm("{ .reg .u64 t; cvta.to.shared.u64 t, %1; cvt.u32.u64 %0, t; }" : "=r"(a) : "l"(p));
    return a;
}
__device__ __forceinline__ void ldsm4(uint32_t* r, uint32_t addr) {
    asm volatile("ldmatrix.sync.aligned.m8n8.x4.shared.b16 {%0,%1,%2,%3}, [%4];"
                 : "=r"(r[0]), "=r"(r[1]), "=r"(r[2]), "=r"(r[3]) : "r"(addr));
}
__device__ __forceinline__ void mma_bf16(float* c, const uint32_t* a, uint32_t b0, uint32_t b1) {
    asm volatile("mma.sync.aligned.m16n8k16.row.col.f32.bf16.bf16.f32 "
                 "{%0,%1,%2,%3}, {%4,%5,%6,%7}, {%8,%9}, {%0,%1,%2,%3};"
                 : "+f"(c[0]), "+f"(c[1]), "+f"(c[2]), "+f"(c[3])
                 : "r"(a[0]), "r"(a[1]), "r"(a[2]), "r"(a[3]), "r"(b0), "r"(b1));
}
// split (a,b) -> packed bf16 hi pair + lo pair
__device__ __forceinline__ void split2(float a, float b, uint32_t& hi, uint32_t& lo) {
    __nv_bfloat162 h = __floats2bfloat162_rn(a, b);
    uint32_t hu = *(uint32_t*)&h;
    float ha = __uint_as_float(hu << 16);
    float hb = __uint_as_float(hu & 0xffff0000u);
    __nv_bfloat162 l = __floats2bfloat162_rn(a - ha, b - hb);
    hi = hu; lo = *(uint32_t*)&l;
}

// ---------------- prep: B fragments + vec partials (single kernel) ----------------
// 288 blocks x 192 threads. tid<128: one B fragment. Blocks 0..31: vec partials.
__global__ void prep_kernel(const float* __restrict__ gamma,
                            const float* __restrict__ beta,
                            const float* __restrict__ w) {
    const int tid = threadIdx.x;
    const int blk = blockIdx.x;

    if (tid < 128) {
        const int idx = blk * 128 + tid;   // 0..36863
        const int kt   = idx / 768;
        const int rem  = idx - kt * 768;
        const int nt   = rem >> 5;
        const int lane = rem & 31;
        const int n  = nt * 8 + (lane >> 2);
        const int k0 = kt * 16 + (lane & 3) * 2;

        float w00 = gamma[k0]     * w[(k0)     * NDIM + n];
        float w01 = gamma[k0 + 1] * w[(k0 + 1) * NDIM + n];
        float w10 = gamma[k0 + 8] * w[(k0 + 8) * NDIM + n];
        float w11 = gamma[k0 + 9] * w[(k0 + 9) * NDIM + n];

        uint32_t bh0, bl0, bh1, bl1;
        split2(w00, w01, bh0, bl0);
        split2(w10, w11, bh1, bl1);
        g_Bf[idx] = make_uint4(bh0, bh1, bl0, bl1);
    }
    if (blk < 32) {
        const int n  = tid;                // 0..191
        const int k0 = blk * 24;
        float sg = 0.f, sb = 0.f;
        #pragma unroll 4
        for (int k = k0; k < k0 + 24; k++) {
            float wv = __ldg(&w[k * NDIM + n]);
            sg += __ldg(&gamma[k]) * wv;
            sb += __ldg(&beta[k])  * wv;
        }
        g_vpart[blk * 384 + n]       = sg;
        g_vpart[blk * 384 + 192 + n] = sb;
    }
}

// ---------------- fused single-pass gather + raw-GEMM + LN-affine epilogue ----------------
// grid 512 CTAs x 256 threads, 2 CTAs/SM; CTA computes rows [bid*64,+64) x 192 cols.
// Warp layout 1(m) x 8(n): no B duplication. Single A buffer, R8 body ordering
// (fill -> bar -> mma -> bar); chunk order rotated per CTA so co-resident CTAs
// anti-align their fill/mma phases. Vec reduction hoisted to kernel start.
__global__ __launch_bounds__(256, 2)
void pm_kernel(const float* __restrict__ x, float* __restrict__ out) {
    extern __shared__ char smem[];
    const uint32_t sbase = smem_u32(smem);
    const int tid  = threadIdx.x;
    const int bid  = blockIdx.x;
    const int lane = tid & 31;
    const int wid  = tid >> 5;
    const int r    = tid & 63;    // A row this thread fills
    const int q    = tid >> 6;    // c-quarter within chunk (0..3)

    float* rstd_s = (float*)(smem + OFF_RSTD);
    float* mrs_s  = (float*)(smem + OFF_MRS);
    float* gW_s   = (float*)(smem + OFF_GW);
    float* bW_s   = (float*)(smem + OFF_BW);

    // ---- hoisted vec reduction: gW/bW into smem (hides under first fill) ----
    #pragma unroll 1
    for (int j = tid; j < 384; j += 256) {
        float S = 0.f;
        #pragma unroll 8
        for (int p = 0; p < 32; p++) S += __ldg(&g_vpart[p * 384 + j]);
        if (j < 192) gW_s[j] = S;
        else         bW_s[j - 192] = S;
    }

    const int grp = bid * 2 + (r >> 5);
    const int h2i = grp & 31, d2i = (grp >> 5) & 15, bi = grp >> 9;
    const float* xr = x + (size_t)bi * CDHW + (2 * d2i) * HW + (2 * h2i) * WDIM + 2 * (r & 31);

    const uint32_t aoff = (uint32_t)(lane & 15) * ASTR + (lane >> 4) * 16;
    const int start = ((bid >> 2) & 1) * 2;   // chunk-schedule rotation

    float acc[4][3][4];
    #pragma unroll
    for (int mt = 0; mt < 4; mt++)
        #pragma unroll
        for (int nt = 0; nt < 3; nt++)
            #pragma unroll
            for (int e = 0; e < 4; e++) acc[mt][nt][e] = 0.f;

    float s = 0.f, s2 = 0.f;
    const int cbase = q * 24;

    // ---- fill chunk ch (octant pair): raw y -> bf16 hi/lo in smem + stats ----
    auto fill = [&](int ch) {
        char* dst = smem + (uint32_t)r * ASTR;
        const float* xc = xr + (ch >> 1) * HW + (ch & 1) * WDIM;
        int c = cbase;
        #pragma unroll
        for (int j = 0; j < 3; j++) {
            uint32_t h0[4], h1[4], l0[4], l1[4];
            #pragma unroll
            for (int t = 0; t < 4; t++, c += 2) {
                float2 va = *(const float2*)(xc + (size_t)c * DHW);
                float2 vb = *(const float2*)(xc + (size_t)(c + 1) * DHW);
                s  += (va.x + va.y) + (vb.x + vb.y);
                s2 += va.x * va.x + va.y * va.y + vb.x * vb.x + vb.y * vb.y;
                split2(va.x, vb.x, h0[t], l0[t]);   // kl = c, c+1   (w=0 octant)
                split2(va.y, vb.y, h1[t], l1[t]);   // kl = 96+c,+1  (w=1 octant)
            }
            const int c0 = cbase + 8 * j;           // 16B-aligned
            *(uint4*)(dst + 2 * c0)                = make_uint4(h0[0], h0[1], h0[2], h0[3]);
            *(uint4*)(dst + 192 + 2 * c0)          = make_uint4(h1[0], h1[1], h1[2], h1[3]);
            *(uint4*)(dst + OFF_AL + 2 * c0)       = make_uint4(l0[0], l0[1], l0[2], l0[3]);
            *(uint4*)(dst + OFF_AL + 192 + 2 * c0) = make_uint4(l1[0], l1[1], l1[2], l1[3]);
        }
    };

    // ---- mma over one chunk (12 k-steps, 3 split terms, B via LDG fragments) ----
    auto mmachunk = [&](int ch) {
        const uint4* bp = g_Bf + ((size_t)(ch * 12) * 24 + wid * 3) * 32 + lane;
        uint32_t bb[2][3][4];
        #pragma unroll
        for (int nt = 0; nt < 3; nt++) {
            uint4 v = __ldg(bp + nt * 32);
            bb[0][nt][0] = v.x; bb[0][nt][1] = v.y; bb[0][nt][2] = v.z; bb[0][nt][3] = v.w;
        }
        #pragma unroll
        for (int ks = 0; ks < 12; ks++) {
            if (ks < 11) {
                const uint4* bp2 = bp + (size_t)(ks + 1) * 24 * 32;
                #pragma unroll
                for (int nt = 0; nt < 3; nt++) {
                    uint4 v = __ldg(bp2 + nt * 32);
                    bb[(ks + 1) & 1][nt][0] = v.x; bb[(ks + 1) & 1][nt][1] = v.y;
                    bb[(ks + 1) & 1][nt][2] = v.z; bb[(ks + 1) & 1][nt][3] = v.w;
                }
            }
            uint32_t af[4][4], al[4][4];
            #pragma unroll
            for (int mt = 0; mt < 4; mt++)
                ldsm4(af[mt], sbase + aoff + mt * (16 * ASTR) + ks * 32);
            #pragma unroll
            for (int mt = 0; mt < 4; mt++)
                ldsm4(al[mt], sbase + OFF_AL + aoff + mt * (16 * ASTR) + ks * 32);
            uint32_t (*B)[4] = bb[ks & 1];
            #pragma unroll
            for (int mt = 0; mt < 4; mt++)
                #pragma unroll
                for (int nt = 0; nt < 3; nt++)
                    mma_bf16(acc[mt][nt], af[mt], B[nt][0], B[nt][1]);
            #pragma unroll
            for (int mt = 0; mt < 4; mt++)
                #pragma unroll
                for (int nt = 0; nt < 3; nt++)
                    mma_bf16(acc[mt][nt], al[mt], B[nt][0], B[nt][1]);
            #pragma unroll
            for (int mt = 0; mt < 4; mt++)
                #pragma unroll
                for (int nt = 0; nt < 3; nt++)
                    mma_bf16(acc[mt][nt], af[mt], B[nt][2], B[nt][3]);
        }
    };

    #pragma unroll 1
    for (int i = 0; i < NCHK; i++) {
        const int ch = (start + i) & 3;
        fill(ch);
        __syncthreads();
        mmachunk(ch);
        __syncthreads();
    }

    // ---- LN stats reduction ----
    float* ps = (float*)(smem + OFF_PS);
    ps[tid] = s; ps[256 + tid] = s2;
    __syncthreads();
    if (tid < 64) {
        float S = 0.f, S2 = 0.f;
        #pragma unroll
        for (int j = 0; j < 4; j++) { S += ps[j * 64 + tid]; S2 += ps[256 + j * 64 + tid]; }
        float mu  = S * (1.f / 768.f);
        float var = S2 * (1.f / 768.f) - mu * mu;
        float rstd = rsqrtf(var + 1e-5f);
        rstd_s[tid] = rstd;
        mrs_s[tid]  = mu * rstd;
    }
    __syncthreads();

    // ---- epilogue: stage C transposed in smem (A region), coalesced affine store ----
    float* Csm = (float*)smem;
    #pragma unroll
    for (int mt = 0; mt < 4; mt++) {
        int row = mt * 16 + (lane >> 2);
        #pragma unroll
        for (int nt = 0; nt < 3; nt++) {
            int n = wid * 24 + nt * 8 + 2 * (lane & 3);
            Csm[n * CSTR + row]           = acc[mt][nt][0];
            Csm[(n + 1) * CSTR + row]     = acc[mt][nt][1];
            Csm[n * CSTR + row + 8]       = acc[mt][nt][2];
            Csm[(n + 1) * CSTR + row + 8] = acc[mt][nt][3];
        }
    }
    __syncthreads();
    #pragma unroll 8
    for (int i = 0; i < 48; i++) {
        int idx = tid + 256 * i;
        int n = idx >> 6, row = idx & 63;
        float val = rstd_s[row] * Csm[n * CSTR + row] - mrs_s[row] * gW_s[n] + bW_s[n];
        int grp2 = bid * 2 + (row >> 5);
        int h2o = grp2 & 31, d2o = (grp2 >> 5) & 15, bo = grp2 >> 9;
        out[(size_t)bo * NDIM * OSP + (size_t)n * OSP + d2o * (H2 * W2) + h2o * W2 + (row & 31)] = val;
    }
}

// ---------------- launch ----------------
extern "C" void kernel_launch(void* const* d_in, const int* in_sizes, int n_in,
                              void* d_out, int out_size) {
    const float* x     = (const float*)d_in[0];
    const float* gamma = (const float*)d_in[1];
    const float* beta  = (const float*)d_in[2];
    const float* w     = (const float*)d_in[3];
    float* out = (float*)d_out;

    cudaFuncSetAttribute(pm_kernel, cudaFuncAttributeMaxDynamicSharedMemorySize, SMEM_TOTAL);

    prep_kernel<<<288, 192>>>(gamma, beta, w);
    pm_kernel<<<NCTA, 256, SMEM_TOTAL>>>(x, out);
}